// round 16
// baseline (speedup 1.0000x reference)
#include <cuda_runtime.h>
#include <cstdint>
#include <cub/cub.cuh>

#define NUM_A 9
#define HH 128
#define WW 128
#define NBOX (NUM_A * HH * WW)   /* 147456 */
#define KTOP 6000
#define NPOST 300
#define NMS_NT 1024
#define OWN 6                    /* 1024*6 = 6144 >= 6000 */
#define NWORDS 188               /* ceil(6000/32) */
#define WIN 32
#define NBUCK 65536
#define CCAP 8192                /* compaction capacity (M ~ 6600 expected) */
#define NBLK (NBOX / 1024)       /* 144 */
#define FULLM 0xFFFFFFFFu

__constant__ float c_sizes[NUM_A] = {4.f, 8.f, 12.f, 16.f, 24.f, 32.f, 48.f, 64.f, 96.f};

__device__ unsigned g_sk[NBOX];              // score keys (descending order = ascending key)
__device__ int      g_hist[NBUCK];
__device__ int      g_selB;                  // threshold bucket
__device__ int      g_bcnt[NBLK], g_bbase[NBLK];
__device__ unsigned g_ck[CCAP], g_cv[CCAP];  // compacted (key, idx), idx-ascending
__device__ unsigned g_ck2[CCAP], g_cv2[CCAP];
__device__ unsigned g_yk_a[KTOP], g_yk_b[KTOP], g_yv_a[KTOP], g_yv_b[KTOP];
__device__ float4 g_props[KTOP];
__device__ __align__(256) unsigned char g_cub_temp[32u * 1024u * 1024u];

// ---------------- decode (bit-exact vs reference) ----------------
__device__ __forceinline__ float4 decode_box(int idx, const float4* __restrict__ deltas,
                                             bool* keep)
{
    int a   = idx / (HH * WW);
    int rem = idx - a * (HH * WW);
    int h   = rem >> 7;
    int w   = rem & 127;
    float s    = c_sizes[a];
    float half = s * 0.5f;
    float ax = ((float)h + 0.5f) - half;
    float ay = ((float)w + 0.5f) - half;
    float4 d = deltas[idx];
    float x1 = fmaxf(ax + d.x, 0.0f);
    float y1 = fmaxf(ay + d.y, 0.0f);
    float bw = fmaxf(s + d.z, 0.0f);
    float bh = fmaxf(s + d.w, 0.0f);
    float x2 = x1 + bw;
    float y2 = y1 + bh;
    x1 = fminf(x1, 128.0f);
    y1 = fminf(y1, 128.0f);
    x2 = fminf(x2, 128.0f);
    y2 = fminf(y2, 128.0f);
    float ow = x2 - x1;
    float oh = y2 - y1;
    *keep = (ow >= 3.0f) && (oh >= 3.0f);
    return make_float4(x1, y1, ow, oh);
}

// exact: rn(n/ar) >= 0.7f, division-free common path
__device__ __forceinline__ bool iou_ge(float n, float ar)
{
    float t = fmaf(-0.7f, ar, n);
    if (t >= 0.0f) return true;
    if (t <= -3.2e-8f * ar) return false;
    return __fdiv_rn(n, ar) >= 0.7f;
}

__global__ void k_init()
{
    int i = blockIdx.x * blockDim.x + threadIdx.x;
    if (i < NBUCK) g_hist[i] = 0;
    if (i < CCAP) { g_ck[i] = 0xFFFFFFFFu; g_cv[i] = 0u; }
}

// score key + fused bucket histogram
__global__ void k_score(const float* __restrict__ scores, const float4* __restrict__ deltas)
{
    int i = blockIdx.x * blockDim.x + threadIdx.x;
    if (i >= NBOX) return;
    bool keep;
    (void)decode_box(i, deltas, &keep);
    float sc = keep ? scores[i] : __int_as_float(0xFF800000);
    unsigned u   = __float_as_uint(sc);
    unsigned asc = u ^ ((unsigned)((int)u >> 31) | 0x80000000u);
    unsigned key = ~asc;          // ascending key == descending score
    g_sk[i] = key;
    atomicAdd(&g_hist[key >> 16], 1);
}

// find bucket containing rank KTOP-1
__global__ void __launch_bounds__(1024, 1) k_scan()
{
    __shared__ int sc[1024];
    int t = threadIdx.x;
    int base = t * 64;
    int sum = 0;
#pragma unroll 8
    for (int k = 0; k < 64; ++k) sum += g_hist[base + k];
    sc[t] = sum;
    __syncthreads();
    for (int off = 1; off < 1024; off <<= 1) {
        int v = (t >= off) ? sc[t - off] : 0;
        __syncthreads();
        sc[t] += v;
        __syncthreads();
    }
    int excl = sc[t] - sum;
    if (excl <= KTOP - 1 && KTOP - 1 < excl + sum) {
        int cum = excl;
        for (int k = 0; k < 64; ++k) {
            int c = g_hist[base + k];
            if (KTOP - 1 < cum + c) { g_selB = base + k; break; }
            cum += c;
        }
    }
}

__global__ void k_cnt()
{
    int i = blockIdx.x * blockDim.x + threadIdx.x;
    int B = g_selB;
    int pred = (int)(g_sk[i] >> 16) <= B;
    int c = __syncthreads_count(pred);
    if (threadIdx.x == 0) g_bcnt[blockIdx.x] = c;
}

__global__ void k_bscan()
{
    __shared__ int sc[NBLK];
    int t = threadIdx.x;           // 256 threads, NBLK=144 used
    int v = (t < NBLK) ? g_bcnt[t] : 0;
    if (t < NBLK) sc[t] = v;
    __syncthreads();
    for (int off = 1; off < NBLK; off <<= 1) {
        int a = (t >= off && t < NBLK) ? sc[t - off] : 0;
        __syncthreads();
        if (t < NBLK) sc[t] += a;
        __syncthreads();
    }
    if (t < NBLK) g_bbase[t] = sc[t] - v;   // exclusive
}

__global__ void k_cwrite()
{
    __shared__ int woff[32];
    int i = blockIdx.x * blockDim.x + threadIdx.x;
    int lane = threadIdx.x & 31, wid = threadIdx.x >> 5;
    int B = g_selB;
    unsigned key = g_sk[i];
    int pred = (int)(key >> 16) <= B;
    unsigned wm = __ballot_sync(FULLM, pred);
    if (lane == 0) woff[wid] = __popc(wm);
    __syncthreads();
    if (wid == 0) {
        int v = (lane < 32) ? woff[lane] : 0;
        int pre = v;
#pragma unroll
        for (int o = 1; o < 32; o <<= 1) {
            int x = __shfl_up_sync(FULLM, pre, o);
            if (lane >= o) pre += x;
        }
        woff[lane] = pre - v;      // exclusive
    }
    __syncthreads();
    if (pred) {
        int pos = g_bbase[blockIdx.x] + woff[wid] + __popc(wm & ((1u << lane) - 1u));
        if (pos < CCAP) { g_ck[pos] = key; g_cv[pos] = (unsigned)i; }
    }
}

__global__ void k_props(const float4* __restrict__ deltas)
{
    int r = blockIdx.x * blockDim.x + threadIdx.x;
    if (r >= KTOP) return;
    int idx = (int)g_cv2[r];
    bool keep;
    float4 p = decode_box(idx, deltas, &keep);
    g_props[r] = p;
    float y2 = p.y + p.w;
    g_yk_a[r] = ~__float_as_uint(y2);
    g_yv_a[r] = (unsigned)r;
}

// ---------------- NMS (round-13 champion, verbatim) ----------------
struct SmemNMS {
    float4   sbox[KTOP];
    unsigned swords[NWORDS];
    int      T[132];
    int      s_nc;
    int      scidx[WIN];
    float4   scbox[WIN];
    int      sJ1c[WIN];
    unsigned srow[WIN];
    int      ssc[NMS_NT];
};

__global__ void __launch_bounds__(NMS_NT, 1) k_nms(float* __restrict__ out)
{
    extern __shared__ char sm_raw[];
    SmemNMS* s = (SmemNMS*)sm_raw;

    const int tid  = threadIdx.x;
    const int lane = tid & 31;
    const int wid  = tid >> 5;

    for (int i = tid; i < NPOST * 4; i += NMS_NT) out[i] = 0.0f;

    for (int m = tid; m < KTOP; m += NMS_NT) {
        float4 p = g_props[(int)g_yv_b[m]];
        s->sbox[m] = make_float4(p.x, p.y, p.x + p.z, p.y + p.w);
    }
    if (tid < NWORDS) s->swords[tid] = (tid == NWORDS - 1) ? 0x0000FFFFu : FULLM;
    __syncthreads();

    if (tid < 132) {
        float v = (float)tid;
        int lo = 0, hi = KTOP;
        while (lo < hi) { int mid = (lo + hi) >> 1; if (s->sbox[mid].w > v) lo = mid + 1; else hi = mid; }
        s->T[tid] = lo;
    }

    const int base = tid * OWN;
    float rx1[OWN], ry1[OWN], rx2[OWN], ry2[OWN], rar[OWN];
    unsigned rv = 0;
    float my_ymin1 = 1e30f;
#pragma unroll
    for (int q = 0; q < OWN; ++q) {
        int j = base + q;
        if (j < KTOP) {
            float4 b = s->sbox[j];
            rx1[q] = b.x; ry1[q] = b.y; rx2[q] = b.z; ry2[q] = b.w;
            rar[q] = fmaxf((b.z - b.x) * (b.w - b.y), 1e-6f);
            rv |= 1u << q;
            my_ymin1 = fminf(my_ymin1, b.y);
        } else {
            rx1[q] = 0.f; ry1[q] = 0.f; rx2[q] = 0.f; ry2[q] = 0.f; rar[q] = 1.f;
        }
    }
    float wmin_y1 = my_ymin1;
#pragma unroll
    for (int o = 16; o; o >>= 1) wmin_y1 = fminf(wmin_y1, __shfl_xor_sync(FULLM, wmin_y1, o));
    const int warp_first_box = (wid << 5) * OWN;
    __syncthreads();

    int p = 0;

    for (;;) {
        if (wid == 0) {
            int nc = 0;
            while (nc < WIN && p < KTOP) {
                int w0 = p >> 5;
                int widx = w0 + lane;
                unsigned w = (widx < NWORDS) ? s->swords[widx] : 0u;
                if (lane == 0) w &= (FULLM << (p & 31));
                int cnt = __popc(w);
                int pre = cnt;
#pragma unroll
                for (int o = 1; o < 32; o <<= 1) {
                    int v = __shfl_up_sync(FULLM, pre, o);
                    if (lane >= o) pre += v;
                }
                int total = __shfl_sync(FULLM, pre, 31);
                int r = nc + (pre - cnt);
                unsigned ww = w;
                while (ww && r < WIN) {
                    int b = __ffs(ww) - 1; ww &= ww - 1;
                    s->scidx[r] = (widx << 5) + b;
                    ++r;
                }
                nc += total; if (nc > WIN) nc = WIN;
                p = (w0 + 32) << 5;
                if (p > KTOP) p = KTOP;
                __syncwarp();
                if (nc == WIN) p = s->scidx[WIN - 1] + 1;
            }
            if (lane < nc) {
                int c = s->scidx[lane];
                float4 b = s->sbox[c];
                s->scbox[lane] = b;
                float thr = b.y - 1.001f;
                int j1;
                if (thr < 0.0f) j1 = KTOP;
                else { int kk = (int)thr; if (kk > 131) kk = 131; j1 = s->T[kk]; }
                s->sJ1c[lane] = j1;
            } else {
                s->scbox[lane] = make_float4(1e30f, 1e30f, -1e30f, -1e30f);
                s->sJ1c[lane] = 0;
                s->scidx[lane] = 0x7FFFFFFF;
            }
            if (lane == 0) s->s_nc = nc;
        }
        __syncthreads();
        int nc = s->s_nc;
        if (nc == 0) break;
        unsigned ncm = (nc >= 32) ? FULLM : ((1u << nc) - 1u);

        {
            float4 cw = s->scbox[wid];
            float4 cj = s->scbox[lane];
            int ok = 0;
            if (lane > wid) {
                float arj = fmaxf((cj.z - cj.x) * (cj.w - cj.y), 1e-6f);
                float iw = fminf(cw.z, cj.z) - fmaxf(cw.x, cj.x) + 1.0f;
                float ih = fminf(cw.w, cj.w) - fmaxf(cw.y, cj.y) + 1.0f;
                if (iw > 0.0f && ih > 0.0f && iou_ge(iw * ih, arj)) ok = 1;
            }
            unsigned rm = __ballot_sync(FULLM, ok) & ncm;
            if (lane == 0) s->srow[wid] = rm;
        }
        __syncthreads();

        unsigned row = s->srow[lane];
        float cy2l = s->scbox[lane].w;
        int   j1l  = s->sJ1c[lane];
        unsigned ymask = __ballot_sync(FULLM, cy2l + 1.0001f > wmin_y1);
        unsigned amask = __ballot_sync(FULLM, j1l > warp_first_box);

        unsigned rem = 0, exec = 0;
#pragma unroll
        for (int l = 0; l < 32; ++l) {
            unsigned rl = __shfl_sync(FULLM, row, l);
            unsigned b = 1u << l;
            if ((ncm & b) && !(rem & b)) { exec |= b; rem |= rl; }
        }

        if (rv) {
            unsigned oldrv = rv;
            unsigned e = exec & ymask & amask;
            while (e) {
                int m = __ffs(e) - 1; e &= e - 1;
                int qlim = s->sJ1c[m] - base; if (qlim > OWN) qlim = OWN;
                if (qlim <= 0) continue;
                float4 cb = s->scbox[m];
                if (cb.w + 1.0001f <= my_ymin1) continue;
                int ci = s->scidx[m];
#pragma unroll
                for (int q = 0; q < OWN; ++q) {
                    if (q < qlim && ((rv >> q) & 1u) && (base + q != ci)) {
                        float iw = fminf(cb.z, rx2[q]) - fmaxf(cb.x, rx1[q]) + 1.0f;
                        float ih = fminf(cb.w, ry2[q]) - fmaxf(cb.y, ry1[q]) + 1.0f;
                        if (iw > 0.0f && ih > 0.0f && iou_ge(iw * ih, rar[q]))
                            rv &= ~(1u << q);
                    }
                }
            }
            unsigned clr = oldrv & ~rv;
            if (clr) {
                unsigned long long m64 = (unsigned long long)clr << (base & 31);
                int wdw = base >> 5;
                unsigned lo = (unsigned)m64, hi = (unsigned)(m64 >> 32);
                if (lo) atomicAnd(&s->swords[wdw], ~lo);
                if (hi) atomicAnd(&s->swords[wdw + 1], ~hi);
            }
        }
        __syncthreads();
    }

    int cnt = __popc(rv);
    s->ssc[tid] = cnt;
    __syncthreads();
    for (int off = 1; off < NMS_NT; off <<= 1) {
        int add = (tid >= off) ? s->ssc[tid - off] : 0;
        __syncthreads();
        s->ssc[tid] += add;
        __syncthreads();
    }
    int pos = s->ssc[tid] - cnt;
#pragma unroll
    for (int q = 0; q < OWN; ++q) {
        if ((rv >> q) & 1u) {
            if (pos < NPOST) {
                float4 pp = g_props[(int)g_yv_b[base + q]];
                out[pos * 4 + 0] = pp.x;
                out[pos * 4 + 1] = pp.y;
                out[pos * 4 + 2] = pp.z;
                out[pos * 4 + 3] = pp.w;
            }
            ++pos;
        }
    }
}

extern "C" void kernel_launch(void* const* d_in, const int* in_sizes, int n_in,
                              void* d_out, int out_size)
{
    const float*  scores = (const float*)d_in[0];
    const float4* deltas = (const float4*)d_in[1];
    float* out = (float*)d_out;
    (void)in_sizes; (void)n_in; (void)out_size;

    void *p_ck, *p_ck2, *p_cv, *p_cv2, *p_yka, *p_ykb, *p_yva, *p_yvb, *p_tmp;
    cudaGetSymbolAddress(&p_ck,  g_ck);
    cudaGetSymbolAddress(&p_ck2, g_ck2);
    cudaGetSymbolAddress(&p_cv,  g_cv);
    cudaGetSymbolAddress(&p_cv2, g_cv2);
    cudaGetSymbolAddress(&p_yka, g_yk_a);
    cudaGetSymbolAddress(&p_ykb, g_yk_b);
    cudaGetSymbolAddress(&p_yva, g_yv_a);
    cudaGetSymbolAddress(&p_yvb, g_yv_b);
    cudaGetSymbolAddress(&p_tmp, g_cub_temp);

    k_init<<<NBUCK / 1024, 1024>>>();
    k_score<<<(NBOX + 255) / 256, 256>>>(scores, deltas);
    k_scan<<<1, 1024>>>();
    k_cnt<<<NBLK, 1024>>>();
    k_bscan<<<1, 256>>>();
    k_cwrite<<<NBLK, 1024>>>();

    size_t tb = sizeof(g_cub_temp);
    cub::DeviceRadixSort::SortPairs(p_tmp, tb,
        (const unsigned*)p_ck, (unsigned*)p_ck2,
        (const unsigned*)p_cv, (unsigned*)p_cv2, CCAP);

    k_props<<<(KTOP + 255) / 256, 256>>>(deltas);

    tb = sizeof(g_cub_temp);
    cub::DeviceRadixSort::SortPairs(p_tmp, tb,
        (const unsigned*)p_yka, (unsigned*)p_ykb,
        (const unsigned*)p_yva, (unsigned*)p_yvb, KTOP);

    size_t smem = sizeof(SmemNMS);
    cudaFuncSetAttribute(k_nms, cudaFuncAttributeMaxDynamicSharedMemorySize, (int)smem);
    k_nms<<<1, NMS_NT, smem>>>(out);
}

// round 17
// speedup vs baseline: 2.1813x; 2.1813x over previous
#include <cuda_runtime.h>
#include <cstdint>

#define NUM_A 9
#define HH 128
#define WW 128
#define NBOX (NUM_A * HH * WW)   /* 147456 */
#define KTOP 6000
#define NPOST 300
#define NMS_NT 1024
#define OWN 6                    /* 1024*6 = 6144 >= 6000 */
#define NWORDS 188
#define WIN 32
#define NB 8192                  /* buckets for both orderings */
#define MCAP 8192
#define FULLM 0xFFFFFFFFu
typedef unsigned long long ull;

__constant__ float c_sizes[NUM_A] = {4.f, 8.f, 12.f, 16.f, 24.f, 32.f, 48.f, 64.f, 96.f};

__device__ unsigned g_sk[NBOX];
__device__ int g_hist1[NB], g_cnt1[NB], g_pref1[NB];
__device__ int g_hist2[NB], g_pref2[NB], g_cnt2f[NB];
__device__ int g_B1, g_M1;
__device__ ull g_mem1[MCAP];
__device__ ull g_mem2[KTOP];
__device__ float4 g_props[KTOP];
__device__ unsigned g_y2k[KTOP];

// ---------------- decode (bit-exact vs reference) ----------------
__device__ __forceinline__ float4 decode_box(int idx, const float4* __restrict__ deltas,
                                             bool* keep)
{
    int a   = idx / (HH * WW);
    int rem = idx - a * (HH * WW);
    int h   = rem >> 7;
    int w   = rem & 127;
    float s    = c_sizes[a];
    float half = s * 0.5f;
    float ax = ((float)h + 0.5f) - half;
    float ay = ((float)w + 0.5f) - half;
    float4 d = deltas[idx];
    float x1 = fmaxf(ax + d.x, 0.0f);
    float y1 = fmaxf(ay + d.y, 0.0f);
    float bw = fmaxf(s + d.z, 0.0f);
    float bh = fmaxf(s + d.w, 0.0f);
    float x2 = x1 + bw;
    float y2 = y1 + bh;
    x1 = fminf(x1, 128.0f);
    y1 = fminf(y1, 128.0f);
    x2 = fminf(x2, 128.0f);
    y2 = fminf(y2, 128.0f);
    float ow = x2 - x1;
    float oh = y2 - y1;
    *keep = (ow >= 3.0f) && (oh >= 3.0f);
    return make_float4(x1, y1, ow, oh);
}

// exact: rn(n/ar) >= 0.7f, division-free common path
__device__ __forceinline__ bool iou_ge(float n, float ar)
{
    float t = fmaf(-0.7f, ar, n);
    if (t >= 0.0f) return true;
    if (t <= -3.2e-8f * ar) return false;
    return __fdiv_rn(n, ar) >= 0.7f;
}

// monotone (non-decreasing) bucket maps — exactness only needs monotonicity;
// within-bucket ranking uses the full composite comparator.
__device__ __forceinline__ int bucket1(unsigned key)
{
    if (key < 0x40800000u) return 0;
    unsigned d = (key - 0x40800000u) >> 10;
    return d > 8191u ? 8191 : (int)d;
}
__device__ __forceinline__ int bucket2(float y2)
{
    int t = (int)(y2 * 63.0f);
    if (t > 8190) t = 8190;
    if (t < 0) t = 0;
    return 8190 - t;      // ascending bucket == descending y2
}

__global__ void k_init()
{
    int i = blockIdx.x * blockDim.x + threadIdx.x;
    if (i < NB) g_hist1[i] = 0;
    else if (i < 2 * NB) g_cnt1[i - NB] = 0;
    else if (i < 3 * NB) g_hist2[i - 2 * NB] = 0;
}

// key + histogram (overflow bucket warp-aggregated to avoid atomic storms)
__global__ void k_score(const float* __restrict__ scores, const float4* __restrict__ deltas)
{
    int i = blockIdx.x * blockDim.x + threadIdx.x;   // NBOX % 256 == 0: all threads valid
    bool keep;
    (void)decode_box(i, deltas, &keep);
    float sc = keep ? scores[i] : __int_as_float(0xFF800000);
    unsigned u   = __float_as_uint(sc);
    unsigned asc = u ^ ((unsigned)((int)u >> 31) | 0x80000000u);
    unsigned key = ~asc;
    g_sk[i] = key;
    int b = bucket1(key);
    bool hot = (b == 8191);
    unsigned hm = __ballot_sync(FULLM, hot);
    if (!hot) atomicAdd(&g_hist1[b], 1);
    else if ((threadIdx.x & 31) == (unsigned)(__ffs(hm) - 1))
        atomicAdd(&g_hist1[8191], __popc(hm));
}

// exclusive prefix over 8192 bins + threshold bucket (rank KTOP-1)
__global__ void __launch_bounds__(1024, 1) k_scan1()
{
    __shared__ int part[1024];
    int t = threadIdx.x;
    int loc[8];
    int sum = 0;
#pragma unroll
    for (int k = 0; k < 8; ++k) { loc[k] = g_hist1[t * 8 + k]; sum += loc[k]; }
    part[t] = sum;
    __syncthreads();
    for (int off = 1; off < 1024; off <<= 1) {
        int v = (t >= off) ? part[t - off] : 0;
        __syncthreads();
        part[t] += v;
        __syncthreads();
    }
    int incl = part[t];
    int excl = incl - sum;
    int run = excl;
#pragma unroll
    for (int k = 0; k < 8; ++k) { g_pref1[t * 8 + k] = run; run += loc[k]; }
    if (excl <= KTOP - 1 && KTOP - 1 < incl) {
        int cum = excl;
        for (int k = 0; k < 8; ++k) {
            if (KTOP - 1 < cum + loc[k]) { g_B1 = t * 8 + k; g_M1 = cum + loc[k]; break; }
            cum += loc[k];
        }
    }
}

// scatter selected (whole buckets <= B1) into per-bucket slots (unordered)
__global__ void k_place1()
{
    int i = blockIdx.x * blockDim.x + threadIdx.x;
    unsigned key = g_sk[i];
    int b = bucket1(key);
    if (b <= g_B1) {
        int pos = g_pref1[b] + atomicAdd(&g_cnt1[b], 1);
        if (pos < MCAP) g_mem1[pos] = ((ull)key << 18) | (unsigned)i;
    }
}

// exact rank within bucket -> score rank r; decode props; y2 key + histogram2
__global__ void k_rank1props(const float4* __restrict__ deltas)
{
    int s = blockIdx.x * blockDim.x + threadIdx.x;
    if (s >= g_M1 || s >= MCAP) return;
    ull me = g_mem1[s];
    unsigned key = (unsigned)(me >> 18);
    int b = bucket1(key);
    int base = g_pref1[b];
    int n = g_hist1[b];
    int c = 0;
    for (int t = base; t < base + n; ++t) c += (g_mem1[t] < me);
    int r = base + c;
    if (r < KTOP) {
        int idx = (int)(me & 0x3FFFFu);
        bool keep;
        float4 p = decode_box(idx, deltas, &keep);
        g_props[r] = p;
        float y2 = p.y + p.w;
        unsigned y2k = ~__float_as_uint(y2);
        g_y2k[r] = y2k;
        atomicAdd(&g_hist2[bucket2(y2)], 1);
    }
}

// 1 CTA: prefix over hist2 + scatter (y2key<<13|r) into bucket slots
__global__ void __launch_bounds__(1024, 1) k_s2p2()
{
    extern __shared__ int sm2[];
    int* spref = sm2;            // 8192
    int* scnt  = sm2 + NB;       // 8192
    int* part  = sm2 + 2 * NB;   // 1024
    int t = threadIdx.x;
    int loc[8];
    int sum = 0;
#pragma unroll
    for (int k = 0; k < 8; ++k) { loc[k] = g_hist2[t * 8 + k]; sum += loc[k]; }
    part[t] = sum;
    __syncthreads();
    for (int off = 1; off < 1024; off <<= 1) {
        int v = (t >= off) ? part[t - off] : 0;
        __syncthreads();
        part[t] += v;
        __syncthreads();
    }
    int run = part[t] - sum;
#pragma unroll
    for (int k = 0; k < 8; ++k) { spref[t * 8 + k] = run; run += loc[k]; scnt[t * 8 + k] = 0; }
    __syncthreads();
    for (int r = t; r < KTOP; r += 1024) {
        unsigned y2k = g_y2k[r];
        float y2 = __uint_as_float(~y2k);
        int bb = bucket2(y2);
        int pos = spref[bb] + atomicAdd(&scnt[bb], 1);
        g_mem2[pos] = ((ull)y2k << 13) | (unsigned)r;
    }
    __syncthreads();
#pragma unroll
    for (int k = 0; k < 8; ++k) {
        g_pref2[t * 8 + k] = spref[t * 8 + k];
        g_cnt2f[t * 8 + k] = scnt[t * 8 + k];
    }
}

// ---------------- NMS (r13 champion + fused rank2 prologue) ----------------
struct SmemNMS {
    float4   sbox[KTOP];
    int      yv[KTOP];
    unsigned swords[NWORDS];
    int      T[132];
    int      s_nc;
    int      scidx[WIN];
    float4   scbox[WIN];
    int      sJ1c[WIN];
    unsigned srow[WIN];
    int      ssc[NMS_NT];
};

__global__ void __launch_bounds__(NMS_NT, 1) k_nms(float* __restrict__ out)
{
    extern __shared__ char sm_raw[];
    SmemNMS* s = (SmemNMS*)sm_raw;

    const int tid  = threadIdx.x;
    const int lane = tid & 31;
    const int wid  = tid >> 5;

    for (int i = tid; i < NPOST * 4; i += NMS_NT) out[i] = 0.0f;

    // rank2: exact stable argsort(-y2) position m for each score-rank r
    for (int s_ = tid; s_ < KTOP; s_ += NMS_NT) {
        ull me = g_mem2[s_];
        float y2 = __uint_as_float(~(unsigned)(me >> 13));
        int bb = bucket2(y2);
        int baseb = g_pref2[bb];
        int n = g_cnt2f[bb];
        int c = 0;
        for (int t2 = baseb; t2 < baseb + n; ++t2) c += (g_mem2[t2] < me);
        s->yv[baseb + c] = (int)(me & 0x1FFFu);
    }
    __syncthreads();

    for (int m = tid; m < KTOP; m += NMS_NT) {
        float4 p = g_props[s->yv[m]];
        s->sbox[m] = make_float4(p.x, p.y, p.x + p.z, p.y + p.w);
    }
    if (tid < NWORDS) s->swords[tid] = (tid == NWORDS - 1) ? 0x0000FFFFu : FULLM;
    __syncthreads();

    if (tid < 132) {
        float v = (float)tid;
        int lo = 0, hi = KTOP;
        while (lo < hi) { int mid = (lo + hi) >> 1; if (s->sbox[mid].w > v) lo = mid + 1; else hi = mid; }
        s->T[tid] = lo;
    }

    const int base = tid * OWN;
    float rx1[OWN], ry1[OWN], rx2[OWN], ry2[OWN], rar[OWN];
    unsigned rv = 0;
    float my_ymin1 = 1e30f;
#pragma unroll
    for (int q = 0; q < OWN; ++q) {
        int j = base + q;
        if (j < KTOP) {
            float4 b = s->sbox[j];
            rx1[q] = b.x; ry1[q] = b.y; rx2[q] = b.z; ry2[q] = b.w;
            rar[q] = fmaxf((b.z - b.x) * (b.w - b.y), 1e-6f);
            rv |= 1u << q;
            my_ymin1 = fminf(my_ymin1, b.y);
        } else {
            rx1[q] = 0.f; ry1[q] = 0.f; rx2[q] = 0.f; ry2[q] = 0.f; rar[q] = 1.f;
        }
    }
    float wmin_y1 = my_ymin1;
#pragma unroll
    for (int o = 16; o; o >>= 1) wmin_y1 = fminf(wmin_y1, __shfl_xor_sync(FULLM, wmin_y1, o));
    const int warp_first_box = (wid << 5) * OWN;
    __syncthreads();

    int p = 0;

    for (;;) {
        if (wid == 0) {
            int nc = 0;
            while (nc < WIN && p < KTOP) {
                int w0 = p >> 5;
                int widx = w0 + lane;
                unsigned w = (widx < NWORDS) ? s->swords[widx] : 0u;
                if (lane == 0) w &= (FULLM << (p & 31));
                int cnt = __popc(w);
                int pre = cnt;
#pragma unroll
                for (int o = 1; o < 32; o <<= 1) {
                    int v = __shfl_up_sync(FULLM, pre, o);
                    if (lane >= o) pre += v;
                }
                int total = __shfl_sync(FULLM, pre, 31);
                int r = nc + (pre - cnt);
                unsigned ww = w;
                while (ww && r < WIN) {
                    int b = __ffs(ww) - 1; ww &= ww - 1;
                    s->scidx[r] = (widx << 5) + b;
                    ++r;
                }
                nc += total; if (nc > WIN) nc = WIN;
                p = (w0 + 32) << 5;
                if (p > KTOP) p = KTOP;
                __syncwarp();
                if (nc == WIN) p = s->scidx[WIN - 1] + 1;
            }
            if (lane < nc) {
                int c = s->scidx[lane];
                float4 b = s->sbox[c];
                s->scbox[lane] = b;
                float thr = b.y - 1.001f;
                int j1;
                if (thr < 0.0f) j1 = KTOP;
                else { int kk = (int)thr; if (kk > 131) kk = 131; j1 = s->T[kk]; }
                s->sJ1c[lane] = j1;
            } else {
                s->scbox[lane] = make_float4(1e30f, 1e30f, -1e30f, -1e30f);
                s->sJ1c[lane] = 0;
                s->scidx[lane] = 0x7FFFFFFF;
            }
            if (lane == 0) s->s_nc = nc;
        }
        __syncthreads();
        int nc = s->s_nc;
        if (nc == 0) break;
        unsigned ncm = (nc >= 32) ? FULLM : ((1u << nc) - 1u);

        {
            float4 cw = s->scbox[wid];
            float4 cj = s->scbox[lane];
            int ok = 0;
            if (lane > wid) {
                float arj = fmaxf((cj.z - cj.x) * (cj.w - cj.y), 1e-6f);
                float iw = fminf(cw.z, cj.z) - fmaxf(cw.x, cj.x) + 1.0f;
                float ih = fminf(cw.w, cj.w) - fmaxf(cw.y, cj.y) + 1.0f;
                if (iw > 0.0f && ih > 0.0f && iou_ge(iw * ih, arj)) ok = 1;
            }
            unsigned rm = __ballot_sync(FULLM, ok) & ncm;
            if (lane == 0) s->srow[wid] = rm;
        }
        __syncthreads();

        unsigned row = s->srow[lane];
        float cy2l = s->scbox[lane].w;
        int   j1l  = s->sJ1c[lane];
        unsigned ymask = __ballot_sync(FULLM, cy2l + 1.0001f > wmin_y1);
        unsigned amask = __ballot_sync(FULLM, j1l > warp_first_box);

        unsigned rem = 0, exec = 0;
#pragma unroll
        for (int l = 0; l < 32; ++l) {
            unsigned rl = __shfl_sync(FULLM, row, l);
            unsigned b = 1u << l;
            if ((ncm & b) && !(rem & b)) { exec |= b; rem |= rl; }
        }

        if (rv) {
            unsigned oldrv = rv;
            unsigned e = exec & ymask & amask;
            while (e) {
                int m = __ffs(e) - 1; e &= e - 1;
                int qlim = s->sJ1c[m] - base; if (qlim > OWN) qlim = OWN;
                if (qlim <= 0) continue;
                float4 cb = s->scbox[m];
                if (cb.w + 1.0001f <= my_ymin1) continue;
                int ci = s->scidx[m];
#pragma unroll
                for (int q = 0; q < OWN; ++q) {
                    if (q < qlim && ((rv >> q) & 1u) && (base + q != ci)) {
                        float iw = fminf(cb.z, rx2[q]) - fmaxf(cb.x, rx1[q]) + 1.0f;
                        float ih = fminf(cb.w, ry2[q]) - fmaxf(cb.y, ry1[q]) + 1.0f;
                        if (iw > 0.0f && ih > 0.0f && iou_ge(iw * ih, rar[q]))
                            rv &= ~(1u << q);
                    }
                }
            }
            unsigned clr = oldrv & ~rv;
            if (clr) {
                unsigned long long m64 = (unsigned long long)clr << (base & 31);
                int wdw = base >> 5;
                unsigned lo = (unsigned)m64, hi = (unsigned)(m64 >> 32);
                if (lo) atomicAnd(&s->swords[wdw], ~lo);
                if (hi) atomicAnd(&s->swords[wdw + 1], ~hi);
            }
        }
        __syncthreads();
    }

    int cnt = __popc(rv);
    s->ssc[tid] = cnt;
    __syncthreads();
    for (int off = 1; off < NMS_NT; off <<= 1) {
        int add = (tid >= off) ? s->ssc[tid - off] : 0;
        __syncthreads();
        s->ssc[tid] += add;
        __syncthreads();
    }
    int pos = s->ssc[tid] - cnt;
#pragma unroll
    for (int q = 0; q < OWN; ++q) {
        if ((rv >> q) & 1u) {
            if (pos < NPOST) {
                float4 pp = g_props[s->yv[base + q]];
                out[pos * 4 + 0] = pp.x;
                out[pos * 4 + 1] = pp.y;
                out[pos * 4 + 2] = pp.z;
                out[pos * 4 + 3] = pp.w;
            }
            ++pos;
        }
    }
}

extern "C" void kernel_launch(void* const* d_in, const int* in_sizes, int n_in,
                              void* d_out, int out_size)
{
    const float*  scores = (const float*)d_in[0];
    const float4* deltas = (const float4*)d_in[1];
    float* out = (float*)d_out;
    (void)in_sizes; (void)n_in; (void)out_size;

    k_init<<<(3 * NB + 1023) / 1024, 1024>>>();
    k_score<<<NBOX / 256, 256>>>(scores, deltas);
    k_scan1<<<1, 1024>>>();
    k_place1<<<NBOX / 256, 256>>>();
    k_rank1props<<<MCAP / 1024, 1024>>>(deltas);

    int s2smem = (2 * NB + 1024) * (int)sizeof(int);
    cudaFuncSetAttribute(k_s2p2, cudaFuncAttributeMaxDynamicSharedMemorySize, s2smem);
    k_s2p2<<<1, 1024, s2smem>>>();

    size_t smem = sizeof(SmemNMS);
    cudaFuncSetAttribute(k_nms, cudaFuncAttributeMaxDynamicSharedMemorySize, (int)smem);
    k_nms<<<1, NMS_NT, smem>>>(out);
}